// round 4
// baseline (speedup 1.0000x reference)
#include <cuda_runtime.h>

#define T_STEPS 2000
#define NB      1024
#define NMUL    16
#define NTH     128   // 4 warps -> SMSPs 0..3
#define NBLK    128   // 128*128 = 16384 threads = NB*NMUL
#define CH      16    // steps per chunk (= ring size = unroll)
#define NCHUNK  (T_STEPS / CH)   // 125, exact

__device__ __forceinline__ float fast_lg2(float a) {
    float r;
    asm("lg2.approx.f32 %0, %1;" : "=f"(r) : "f"(a));
    return r;
}
__device__ __forceinline__ float fast_ex2(float a) {
    float r;
    asm("ex2.approx.f32 %0, %1;" : "=f"(r) : "f"(a));
    return r;
}

__global__ void __launch_bounds__(NTH, 1)
hbv_kernel(const float* __restrict__ x,      // (T, B, 3)
           const float* __restrict__ ps,     // (B, 288)
           float* __restrict__ out)          // (T, B)
{
    // per-warp transpose buffer for the m-reduction (pad 17 -> conflict-free)
    __shared__ float red[4][2][16][17];
    // per-warp double-buffered forcing stage: [buf][warp][j*6 + cell*3 + comp]
    __shared__ float xf[2][4][CH * 6];

    const int m    = threadIdx.x & (NMUL - 1);
    const int w_id = threadIdx.x >> 5;
    const int lane = threadIdx.x & 31;
    const int cell = lane >> 4;
    const int tt   = lane & 15;

    const int gwarp = blockIdx.x * 4 + w_id;   // global warp id
    const int b     = gwarp * 2 + cell;        // this thread's grid cell
    const int b0    = gwarp * 2;               // warp's first cell

    const float* pb = ps + b * 288 + m;

    // --- physical parameters (parRT, parAC unused by the model) ---
    const float BETA   = 1.0f   + pb[0*16]  * 5.0f;
    const float FC     = 50.0f  + pb[1*16]  * 950.0f;
    const float K0     = 0.05f  + pb[2*16]  * 0.85f;
    const float K1     = 0.01f  + pb[3*16]  * 0.49f;
    const float K2     = 0.001f + pb[4*16]  * 0.199f;
    const float LP     = 0.2f   + pb[5*16]  * 0.8f;
    const float PERC   =          pb[6*16]  * 10.0f;
    const float UZL    =          pb[7*16]  * 100.0f;
    const float TT     = -2.5f  + pb[8*16]  * 5.0f;
    const float CFMAX  = 0.5f   + pb[9*16]  * 9.5f;
    const float CFR    =          pb[10*16] * 0.1f;
    const float CWH    =          pb[11*16] * 0.2f;
    const float BETAET = 0.3f   + pb[12*16] * 4.7f;
    const float Cpar   =          pb[13*16];

    const float invFC    = 1.0f / FC;
    const float lg2rLP   = fast_lg2(1.0f / LP);
    const float epsF     = 1e-5f * invFC;
    const float CFRCFMAX = CFR * CFMAX;

    // --- routing weights (gammaln prefactor cancels under normalization) ---
    const float aa     = fmaxf(pb[256] * 2.9f, 0.0f) + 0.1f;
    const float theta  = fmaxf(pb[272] * 6.5f, 0.0f) + 0.5f;
    const float itheta = 1.0f / theta;

    float w[CH];
    float wsum = 0.0f;
#pragma unroll
    for (int k = 0; k < 15; ++k) {
        const float tk = (float)k + 0.5f;
        w[k] = expf((aa - 1.0f) * logf(tk) - tk * itheta);
        wsum += w[k];
    }
    const float iws = 1.0f / wsum;
#pragma unroll
    for (int k = 0; k < 15; ++k) w[k] *= iws;
    w[15] = 0.0f;                         // dummy tap so ring period == unroll

    // --- forcing stage loader: 3 floats per lane per chunk ---
    // idx = lane*3+i -> j = idx/6 (step), r = idx%6 (cell*3+comp)
    const int i0 = lane * 3;
    const int j0 = i0 / 6,       r0c = i0 % 6;
    const int j1 = (i0 + 1) / 6, r1c = (i0 + 1) % 6;
    const int j2 = (i0 + 2) / 6, r2c = (i0 + 2) % 6;
    const float* xg0 = x + (size_t)b0 * 3 + r0c + (size_t)j0 * (NB * 3);
    const float* xg1 = x + (size_t)b0 * 3 + r1c + (size_t)j1 * (NB * 3);
    const float* xg2 = x + (size_t)b0 * 3 + r2c + (size_t)j2 * (NB * 3);

    // preload chunk 0 into buffer 0
    {
        const float v0 = xg0[0], v1 = xg1[0], v2 = xg2[0];
        xf[0][w_id][j0 * 6 + r0c] = v0;
        xf[0][w_id][j1 * 6 + r1c] = v1;
        xf[0][w_id][j2 * 6 + r2c] = v2;
    }
    __syncwarp();

    // --- state (y = SM/FC normalized) ---
    float SP  = 1e-5f, MW = 1e-5f, SUZ = 1e-5f, SLZ = 1e-5f;
    float y   = epsF;

    float q[CH];
#pragma unroll
    for (int k = 0; k < CH; ++k) q[k] = 0.0f;

    const int c3 = cell * 3;

#pragma unroll 1
    for (int c = 0; c < NCHUNK; ++c) {
        const int buf = c & 1;

        // kick off next chunk's forcing loads (latency hidden by 16 steps)
        {
            const size_t toff = (size_t)((c + 1 < NCHUNK) ? (c + 1) : c) * CH * (NB * 3);
            const float v0 = __ldg(xg0 + toff);
            const float v1 = __ldg(xg1 + toff);
            const float v2 = __ldg(xg2 + toff);
            float* dst = xf[buf ^ 1][w_id];
            dst[j0 * 6 + r0c] = v0;
            dst[j1 * 6 + r1c] = v1;
            dst[j2 * 6 + r2c] = v2;
        }

        const float* fx = xf[buf][w_id];

#pragma unroll
        for (int j = 0; j < CH; ++j) {
            const float Pm = fx[j * 6 + c3 + 0];
            const float Tc = fx[j * 6 + c3 + 1];
            const float PE = fx[j * 6 + c3 + 2];

            // --- snow routine ---
            const float rain = (Tc >= TT) ? Pm : 0.0f;
            const float snow = Pm - rain;
            const float m0 = fmaxf(CFMAX * (Tc - TT), 0.0f);       // off-chain
            const float r0 = fmaxf(CFRCFMAX * (TT - Tc), 0.0f);    // off-chain
            SP += snow;
            const float melt = fminf(m0, SP);
            MW += melt;  SP -= melt;
            const float refreeze = fminf(r0, MW);
            SP += refreeze;  MW -= refreeze;
            const float tosoil = fmaxf(fmaf(-CWH, SP, MW), 0.0f);
            MW -= tosoil;

            // --- soil routine (y = SM/FC) ---
            const float inr  = rain + tosoil;
            const float inrF = inr * invFC;                 // off y-chain
            const float yp   = y + inrF;                    // parallel with lg2
            const float sw   = fminf(fast_ex2(BETA * fast_lg2(y)), 1.0f);
            const float recharge = inr * sw;                // off y-chain
            y = fmaf(-inrF, sw, yp);                        // = y + inrF*(1-sw)
            const float excess = fmaxf(y - 1.0f, 0.0f) * FC;
            y = fminf(y, 1.0f);
            // capillary: u = C*(1-y) <= 1 always (C<=1, y<=1) -> no clamp
            const float u    = fmaf(-Cpar, y, Cpar);
            const float SLZF = SLZ * invFC;                 // off y-chain
            y = fmaf(SLZF, u, y);
            const float cap = SLZ * u;
            SLZ -= cap;
            // ef = min(y/LP,1)^BETAET in lg2 domain (min commutes w/ monotone lg2)
            const float ef  = fast_ex2(BETAET * fminf(fast_lg2(y) + lg2rLP, 0.0f));
            const float PEF = PE * invFC;                   // off y-chain
            y = fmaxf(fmaf(-PEF, ef, y), epsF);             // fused ET + floor

            // --- response routine ---
            SUZ += recharge + excess;
            const float PERCv = fminf(SUZ, PERC);
            SUZ -= PERCv;
            const float Q0 = K0 * fmaxf(SUZ - UZL, 0.0f);
            SUZ -= Q0;
            const float Q1 = K1 * SUZ;
            SUZ -= Q1;
            SLZ += PERCv;
            const float Q2 = K2 * SLZ;
            SLZ -= Q2;
            const float Qs = Q0 + Q1 + Q2;

            // --- routing conv: ring of 16 (renamed via unroll), 4 accumulators ---
            q[j] = Qs;
            float a0 = 0.f, a1 = 0.f, a2 = 0.f, a3 = 0.f;
#pragma unroll
            for (int k = 0; k < CH; k += 4) {
                a0 = fmaf(w[k + 0], q[(j - k - 0) & 15], a0);
                a1 = fmaf(w[k + 1], q[(j - k - 1) & 15], a1);
                a2 = fmaf(w[k + 2], q[(j - k - 2) & 15], a2);
                a3 = fmaf(w[k + 3], q[(j - k - 3) & 15], a3);
            }
            red[w_id][cell][m][j] = (a0 + a1) + (a2 + a3);  // STS: issue-only
        }

        // --- per-16-step transpose reduce over m (no per-step shuffles) ---
        __syncwarp();
        {
            float s0 = 0.f, s1 = 0.f;
#pragma unroll
            for (int mi = 0; mi < 16; mi += 2) {
                s0 += red[w_id][cell][mi + 0][tt];
                s1 += red[w_id][cell][mi + 1][tt];
            }
            out[(c * CH + tt) * NB + (b0 + cell)] = (s0 + s1) * 0.0625f;
        }
        __syncwarp();
    }
}

extern "C" void kernel_launch(void* const* d_in, const int* in_sizes, int n_in,
                              void* d_out, int out_size)
{
    const float* x  = (const float*)d_in[0];
    const float* ps = (const float*)d_in[1];
    if (n_in >= 2 && in_sizes[0] == NB * 288) {  // swapped order
        x  = (const float*)d_in[1];
        ps = (const float*)d_in[0];
    }
    float* out = (float*)d_out;
    hbv_kernel<<<NBLK, NTH>>>(x, ps, out);
}

// round 5
// speedup vs baseline: 1.2760x; 1.2760x over previous
#include <cuda_runtime.h>

#define T_STEPS 2000
#define NB      1024
#define NMUL    16
#define NTH     128   // 4 warps -> SMSPs 0..3
#define NBLK    128   // 128*128 = 16384 threads = NB*NMUL
#define CH      16    // steps per chunk (= conv ring size = unroll)
#define NCHUNK  (T_STEPS / CH)   // 125, exact
#define PF      4     // forcing prefetch depth (distance ~4 steps ≈ 500 cyc)

__device__ __forceinline__ float fast_lg2(float a) {
    float r;
    asm("lg2.approx.f32 %0, %1;" : "=f"(r) : "f"(a));
    return r;
}
__device__ __forceinline__ float fast_ex2(float a) {
    float r;
    asm("ex2.approx.f32 %0, %1;" : "=f"(r) : "f"(a));
    return r;
}

__global__ void __launch_bounds__(NTH, 1)
hbv_kernel(const float* __restrict__ x,      // (T, B, 3)
           const float* __restrict__ ps,     // (B, 288)
           float* __restrict__ out)          // (T, B)
{
    // per-warp transpose buffer for the m-reduction (pad 17 -> conflict-free)
    __shared__ float red[4][2][16][17];

    const int m    = threadIdx.x & (NMUL - 1);
    const int w_id = threadIdx.x >> 5;
    const int lane = threadIdx.x & 31;
    const int cell = lane >> 4;
    const int tt   = lane & 15;

    const int gwarp = blockIdx.x * 4 + w_id;
    const int b     = gwarp * 2 + cell;        // this thread's grid cell
    const int b0    = gwarp * 2;               // warp's first cell

    const float* pb = ps + b * 288 + m;

    // --- physical parameters (parRT, parAC unused by the model) ---
    const float BETA   = 1.0f   + pb[0*16]  * 5.0f;
    const float FC     = 50.0f  + pb[1*16]  * 950.0f;
    const float K0     = 0.05f  + pb[2*16]  * 0.85f;
    const float K1     = 0.01f  + pb[3*16]  * 0.49f;
    const float K2     = 0.001f + pb[4*16]  * 0.199f;
    const float LP     = 0.2f   + pb[5*16]  * 0.8f;
    const float PERC   =          pb[6*16]  * 10.0f;
    const float UZL    =          pb[7*16]  * 100.0f;
    const float TT     = -2.5f  + pb[8*16]  * 5.0f;
    const float CFMAX  = 0.5f   + pb[9*16]  * 9.5f;
    const float CFR    =          pb[10*16] * 0.1f;
    const float CWH    =          pb[11*16] * 0.2f;
    const float BETAET = 0.3f   + pb[12*16] * 4.7f;
    const float Cpar   =          pb[13*16];

    const float invFC    = 1.0f / FC;
    const float lg2rLP   = fast_lg2(1.0f / LP);
    const float epsF     = 1e-5f * invFC;
    const float CFRCFMAX = CFR * CFMAX;

    // --- routing weights (gammaln prefactor cancels under normalization) ---
    const float aa     = fmaxf(pb[256] * 2.9f, 0.0f) + 0.1f;
    const float theta  = fmaxf(pb[272] * 6.5f, 0.0f) + 0.5f;
    const float itheta = 1.0f / theta;

    float w[CH];
    float wsum = 0.0f;
#pragma unroll
    for (int k = 0; k < 15; ++k) {
        const float tk = (float)k + 0.5f;
        w[k] = expf((aa - 1.0f) * logf(tk) - tk * itheta);
        wsum += w[k];
    }
    const float iws = 1.0f / wsum;
#pragma unroll
    for (int k = 0; k < 15; ++k) w[k] *= iws;
    w[15] = 0.0f;                         // dummy tap so ring period == unroll

    // --- state (y = SM/FC normalized) ---
    float SP  = 1e-5f, MW = 1e-5f, SUZ = 1e-5f, SLZ = 1e-5f;
    float y   = epsF;

    float q[CH];
#pragma unroll
    for (int k = 0; k < CH; ++k) q[k] = 0.0f;

    // --- forcing prefetch ring: depth PF=4, register resident ---
    const float* xr = x + (size_t)b * 3;
    float Pf[PF], Tf[PF], Ef[PF];
#pragma unroll
    for (int k = 0; k < PF; ++k) {
        const float* xp = xr + (size_t)k * (NB * 3);
        Pf[k] = __ldg(xp + 0);
        Tf[k] = __ldg(xp + 1);
        Ef[k] = __ldg(xp + 2);
    }

#pragma unroll 1
    for (int c = 0; c < NCHUNK; ++c) {
#pragma unroll
        for (int j = 0; j < CH; ++j) {
            const int t = c * CH + j;
            const int s = j & (PF - 1);            // == t & 3 (CH multiple of PF)

            const float Pm = Pf[s], Tc = Tf[s], PE = Ef[s];

            // refill slot with forcing for step t+PF (clamped; consumed 4 steps later)
            {
                const int tn = (t + PF < T_STEPS) ? (t + PF) : (T_STEPS - 1);
                const float* xp = xr + (size_t)tn * (NB * 3);
                Pf[s] = __ldg(xp + 0);
                Tf[s] = __ldg(xp + 1);
                Ef[s] = __ldg(xp + 2);
            }

            // --- snow routine ---
            const float rain = (Tc >= TT) ? Pm : 0.0f;
            const float snow = Pm - rain;
            const float m0 = fmaxf(CFMAX * (Tc - TT), 0.0f);       // off-chain
            const float r0 = fmaxf(CFRCFMAX * (TT - Tc), 0.0f);    // off-chain
            SP += snow;
            const float melt = fminf(m0, SP);
            MW += melt;  SP -= melt;
            const float refreeze = fminf(r0, MW);
            SP += refreeze;  MW -= refreeze;
            const float tosoil = fmaxf(fmaf(-CWH, SP, MW), 0.0f);
            MW -= tosoil;

            // --- soil routine (y = SM/FC) ---
            const float inr  = rain + tosoil;
            const float inrF = inr * invFC;                 // off y-chain
            const float yp   = y + inrF;                    // parallel with lg2
            const float sw   = fminf(fast_ex2(BETA * fast_lg2(y)), 1.0f);
            const float recharge = inr * sw;                // off y-chain
            y = fmaf(-inrF, sw, yp);                        // = y + inrF*(1-sw)
            const float excess = fmaxf(y - 1.0f, 0.0f) * FC;
            y = fminf(y, 1.0f);
            // capillary: u = C*(1-y) <= 1 always (C<=1, y<=1) -> no clamp
            const float u    = fmaf(-Cpar, y, Cpar);
            const float SLZF = SLZ * invFC;                 // off y-chain
            y = fmaf(SLZF, u, y);
            const float cap = SLZ * u;
            SLZ -= cap;
            // ef = min(y/LP,1)^BETAET in lg2 domain (min commutes w/ monotone lg2)
            const float ef  = fast_ex2(BETAET * fminf(fast_lg2(y) + lg2rLP, 0.0f));
            const float PEF = PE * invFC;                   // off y-chain
            y = fmaxf(fmaf(-PEF, ef, y), epsF);             // fused ET + floor

            // --- response routine ---
            SUZ += recharge + excess;
            const float PERCv = fminf(SUZ, PERC);
            SUZ -= PERCv;
            const float Q0 = K0 * fmaxf(SUZ - UZL, 0.0f);
            SUZ -= Q0;
            const float Q1 = K1 * SUZ;
            SUZ -= Q1;
            SLZ += PERCv;
            const float Q2 = K2 * SLZ;
            SLZ -= Q2;
            const float Qs = Q0 + Q1 + Q2;

            // --- routing conv: ring of 16 (renamed via unroll), 4 accumulators ---
            q[j] = Qs;
            float a0 = 0.f, a1 = 0.f, a2 = 0.f, a3 = 0.f;
#pragma unroll
            for (int k = 0; k < CH; k += 4) {
                a0 = fmaf(w[k + 0], q[(j - k - 0) & 15], a0);
                a1 = fmaf(w[k + 1], q[(j - k - 1) & 15], a1);
                a2 = fmaf(w[k + 2], q[(j - k - 2) & 15], a2);
                a3 = fmaf(w[k + 3], q[(j - k - 3) & 15], a3);
            }
            red[w_id][cell][m][j] = (a0 + a1) + (a2 + a3);  // STS: issue-only
        }

        // --- per-16-step transpose reduce over m (no per-step shuffles) ---
        __syncwarp();
        {
            float s0 = 0.f, s1 = 0.f;
#pragma unroll
            for (int mi = 0; mi < 16; mi += 2) {
                s0 += red[w_id][cell][mi + 0][tt];
                s1 += red[w_id][cell][mi + 1][tt];
            }
            out[(c * CH + tt) * NB + (b0 + cell)] = (s0 + s1) * 0.0625f;
        }
        __syncwarp();
    }
}

extern "C" void kernel_launch(void* const* d_in, const int* in_sizes, int n_in,
                              void* d_out, int out_size)
{
    const float* x  = (const float*)d_in[0];
    const float* ps = (const float*)d_in[1];
    if (n_in >= 2 && in_sizes[0] == NB * 288) {  // swapped order
        x  = (const float*)d_in[1];
        ps = (const float*)d_in[0];
    }
    float* out = (float*)d_out;
    hbv_kernel<<<NBLK, NTH>>>(x, ps, out);
}